// round 10
// baseline (speedup 1.0000x reference)
#include <cuda_runtime.h>
#include <cuda_bf16.h>

// LSTM_24936580121326 R10: R9 matvec (constant gate-pair f32x2, 2 elem/thread)
// + activation tail packed across the two elements:
//   2*ig*gg = fma(ti,tg,tg) ; 2*fg*c = fma(tf,c,c) ; h~ = 2h = fma(to,tc,tc)
// with the h~ 0.5-fold absorbed into all h-consuming weights at staging.

#define T_STEPS 49

typedef unsigned long long u64;

struct WPack {
    ulonglong2 w1if[8][4];   // W_hh0 (i,f) : 0.5(row) * 0.5(h~) = 0.25
    ulonglong2 w1go[8][4];   // W_hh0 (g,o) : g 0.5, o 0.25
    ulonglong2 w2uif[8][4];  // W_ih1 (i,f) : 0.25
    ulonglong2 w2ugo[8][4];  // W_ih1 (g,o) : g 0.5, o 0.25
    ulonglong2 w2vif[8][4];  // W_hh1 (i,f) : 0.25
    ulonglong2 w2vgo[8][4];  // W_hh1 (g,o) : g 0.5, o 0.25
    u64 wx_if[8], wx_go[8];  // W_ih0 (x not doubled): i/f 0.5 ; g 1.0, o 0.5
    u64 b1if[8], b1go[8];    // biases: i/f/o 0.5 ; g 1.0
    u64 b2if[8], b2go[8];
    float wlin[8];           // * 0.5 (h~ fold)
    float blin;
};

__device__   WPack g_wtmp;
__constant__ WPack c_w;

__device__ __forceinline__ u64 pack2(float lo, float hi) {
    u64 r; asm("mov.b64 %0, {%1, %2};" : "=l"(r) : "f"(lo), "f"(hi)); return r;
}
__device__ __forceinline__ void unpack2(u64 v, float& lo, float& hi) {
    asm("mov.b64 {%0, %1}, %2;" : "=f"(lo), "=f"(hi) : "l"(v));
}
__device__ __forceinline__ u64 fma2(u64 a, u64 b, u64 c) {
    u64 d; asm("fma.rn.f32x2 %0, %1, %2, %3;" : "=l"(d) : "l"(a), "l"(b), "l"(c)); return d;
}
__device__ __forceinline__ u64 add2(u64 a, u64 b) {
    u64 d; asm("add.rn.f32x2 %0, %1, %2;" : "=l"(d) : "l"(a), "l"(b)); return d;
}
__device__ __forceinline__ u64 mul2(u64 a, u64 b) {
    u64 d; asm("mul.rn.f32x2 %0, %1, %2;" : "=l"(d) : "l"(a), "l"(b)); return d;
}
__device__ __forceinline__ float tanhf_hw(float x) {
    float y; asm("tanh.approx.f32 %0, %1;" : "=f"(y) : "f"(x)); return y;
}

// ---------------- preproc ----------------
__global__ void prep_weights_kernel(
    const float* __restrict__ W_ih0, const float* __restrict__ W_hh0,
    const float* __restrict__ b_ih0, const float* __restrict__ b_hh0,
    const float* __restrict__ W_ih1, const float* __restrict__ W_hh1,
    const float* __restrict__ b_ih1, const float* __restrict__ b_hh1,
    const float* __restrict__ W_lin, const float* __restrict__ b_lin)
{
    int tid = threadIdx.x;
    if (tid < 128) {
        int u = tid >> 4, q = (tid >> 2) & 3, s = tid & 3;
        int col = 2 * q + (s >> 1);
        int sel = s & 1;                 // 0 -> first gate of pair, 1 -> second
        int idx = (u * 4 + q) * 4 + s;
        int gIF = u + 8 * sel;           // i or f  (row 0.5) * h~ 0.5 = 0.25
        int gGO = u + 16 + 8 * sel;      // g or o
        float scIF = 0.25f;
        float scGO = sel ? 0.25f : 0.5f; // g: 1*0.5 ; o: 0.5*0.5
        ((float*)g_wtmp.w1if)[idx]  = scIF * W_hh0[gIF * 8 + col];
        ((float*)g_wtmp.w1go)[idx]  = scGO * W_hh0[gGO * 8 + col];
        ((float*)g_wtmp.w2uif)[idx] = scIF * W_ih1[gIF * 8 + col];
        ((float*)g_wtmp.w2ugo)[idx] = scGO * W_ih1[gGO * 8 + col];
        ((float*)g_wtmp.w2vif)[idx] = scIF * W_hh1[gIF * 8 + col];
        ((float*)g_wtmp.w2vgo)[idx] = scGO * W_hh1[gGO * 8 + col];
    }
    if (tid < 8) {
        int u = tid;
        float* p;
        // x weights: no h~ fold (x is raw input)
        p = (float*)g_wtmp.wx_if; p[2*u] = 0.5f * W_ih0[u];      p[2*u+1] = 0.5f * W_ih0[u+8];
        p = (float*)g_wtmp.wx_go; p[2*u] =        W_ih0[u+16];   p[2*u+1] = 0.5f * W_ih0[u+24];
        p = (float*)g_wtmp.b1if;  p[2*u] = 0.5f*(b_ih0[u]+b_hh0[u]);
                                  p[2*u+1] = 0.5f*(b_ih0[u+8]+b_hh0[u+8]);
        p = (float*)g_wtmp.b1go;  p[2*u] =       (b_ih0[u+16]+b_hh0[u+16]);
                                  p[2*u+1] = 0.5f*(b_ih0[u+24]+b_hh0[u+24]);
        p = (float*)g_wtmp.b2if;  p[2*u] = 0.5f*(b_ih1[u]+b_hh1[u]);
                                  p[2*u+1] = 0.5f*(b_ih1[u+8]+b_hh1[u+8]);
        p = (float*)g_wtmp.b2go;  p[2*u] =       (b_ih1[u+16]+b_hh1[u+16]);
                                  p[2*u+1] = 0.5f*(b_ih1[u+24]+b_hh1[u+24]);
        g_wtmp.wlin[u] = 0.5f * W_lin[u];   // h~ fold
    }
    if (tid == 0) g_wtmp.blin = b_lin[0];
}

// Packed activation tail for one unit. Accs aif={zi,zf}, ago={zg,zo} per elem
// (i/f/o pre-halved). Cpk = {cA,cB} true-scale cell. Produces {h~,h~} splats.
__device__ __forceinline__ void act_unit(
    u64 aifA, u64 agoA, u64 aifB, u64 agoB,
    u64& Cpk, u64 HALF, u64& splA, u64& splB)
{
    float ziA, zfA, zgA, zoA, ziB, zfB, zgB, zoB;
    unpack2(aifA, ziA, zfA); unpack2(agoA, zgA, zoA);
    unpack2(aifB, ziB, zfB); unpack2(agoB, zgB, zoB);
    u64 Ti = pack2(tanhf_hw(ziA), tanhf_hw(ziB));
    u64 Tf = pack2(tanhf_hw(zfA), tanhf_hw(zfB));
    u64 Tg = pack2(tanhf_hw(zgA), tanhf_hw(zgB));
    u64 To = pack2(tanhf_hw(zoA), tanhf_hw(zoB));
    u64 P = fma2(Ti, Tg, Tg);        // 2*ig*gg
    u64 Q = fma2(Tf, Cpk, Cpk);      // 2*fg*c
    Cpk = mul2(HALF, add2(P, Q));    // c' (true scale)
    float cA, cB; unpack2(Cpk, cA, cB);
    u64 Tc = pack2(tanhf_hw(cA), tanhf_hw(cB));
    u64 H = fma2(To, Tc, Tc);        // {h~A, h~B}
    float hA, hB; unpack2(H, hA, hB);
    splA = pack2(hA, hA);
    splB = pack2(hB, hB);
}

// ---------------- fused LSTM: 2 elements per thread ----------------
__global__ void __launch_bounds__(256) lstm_fused_kernel(
    const float* __restrict__ X, float* __restrict__ out, int Bn)
{
    int tid  = threadIdx.x;
    int base = blockIdx.x * 512;
    int bA = base + tid;
    int bB = base + tid + 256;
    bool vA = bA < Bn, vB = bB < Bn;

    u64 hp1A[8], hp2A[8], hp1B[8], hp2B[8];   // {h~,h~} splats
    u64 C1[8], C2[8];                         // {cA,cB} packed cell state
    u64 zero = pack2(0.f, 0.f);
    u64 HALF = pack2(0.5f, 0.5f);
#pragma unroll
    for (int u = 0; u < 8; ++u) {
        hp1A[u] = hp2A[u] = hp1B[u] = hp2B[u] = zero;
        C1[u] = C2[u] = zero;
    }

    const float* __restrict__ xpA = X + (long long)(vA ? bA : 0) * T_STEPS;
    const float* __restrict__ xpB = X + (long long)(vB ? bB : 0) * T_STEPS;

    for (int t = 0; t < T_STEPS; ++t) {
        float xA = __ldg(xpA + t);
        float xB = __ldg(xpB + t);
        u64 xxA = pack2(xA, xA);
        u64 xxB = pack2(xB, xB);

        // ---------- layer 1 ----------
        u64 hn1A[8], hn1B[8];
#pragma unroll
        for (int u = 0; u < 8; ++u) {
            u64 wxi = c_w.wx_if[u], wxg = c_w.wx_go[u];
            u64 bi  = c_w.b1if[u],  bg  = c_w.b1go[u];
            u64 aifA = fma2(wxi, xxA, bi);
            u64 agoA = fma2(wxg, xxA, bg);
            u64 aifB = fma2(wxi, xxB, bi);
            u64 agoB = fma2(wxg, xxB, bg);
#pragma unroll
            for (int q = 0; q < 4; ++q) {
                ulonglong2 wi = c_w.w1if[u][q];
                ulonglong2 wg = c_w.w1go[u][q];
                aifA = fma2(wi.x, hp1A[2*q],   aifA);
                aifA = fma2(wi.y, hp1A[2*q+1], aifA);
                agoA = fma2(wg.x, hp1A[2*q],   agoA);
                agoA = fma2(wg.y, hp1A[2*q+1], agoA);
                aifB = fma2(wi.x, hp1B[2*q],   aifB);
                aifB = fma2(wi.y, hp1B[2*q+1], aifB);
                agoB = fma2(wg.x, hp1B[2*q],   agoB);
                agoB = fma2(wg.y, hp1B[2*q+1], agoB);
            }
            act_unit(aifA, agoA, aifB, agoB, C1[u], HALF, hn1A[u], hn1B[u]);
        }

        // ---------- layer 2 ----------
        u64 hn2A[8], hn2B[8];
#pragma unroll
        for (int u = 0; u < 8; ++u) {
            u64 bi = c_w.b2if[u], bg = c_w.b2go[u];
            u64 aifA = bi, agoA = bg, aifB = bi, agoB = bg;
#pragma unroll
            for (int q = 0; q < 4; ++q) {
                ulonglong2 ui = c_w.w2uif[u][q];
                ulonglong2 ug = c_w.w2ugo[u][q];
                aifA = fma2(ui.x, hn1A[2*q],   aifA);
                aifA = fma2(ui.y, hn1A[2*q+1], aifA);
                agoA = fma2(ug.x, hn1A[2*q],   agoA);
                agoA = fma2(ug.y, hn1A[2*q+1], agoA);
                aifB = fma2(ui.x, hn1B[2*q],   aifB);
                aifB = fma2(ui.y, hn1B[2*q+1], aifB);
                agoB = fma2(ug.x, hn1B[2*q],   agoB);
                agoB = fma2(ug.y, hn1B[2*q+1], agoB);
            }
#pragma unroll
            for (int q = 0; q < 4; ++q) {
                ulonglong2 vi = c_w.w2vif[u][q];
                ulonglong2 vg = c_w.w2vgo[u][q];
                aifA = fma2(vi.x, hp2A[2*q],   aifA);
                aifA = fma2(vi.y, hp2A[2*q+1], aifA);
                agoA = fma2(vg.x, hp2A[2*q],   agoA);
                agoA = fma2(vg.y, hp2A[2*q+1], agoA);
                aifB = fma2(vi.x, hp2B[2*q],   aifB);
                aifB = fma2(vi.y, hp2B[2*q+1], aifB);
                agoB = fma2(vg.x, hp2B[2*q],   agoB);
                agoB = fma2(vg.y, hp2B[2*q+1], agoB);
            }
            act_unit(aifA, agoA, aifB, agoB, C2[u], HALF, hn2A[u], hn2B[u]);
        }

#pragma unroll
        for (int u = 0; u < 8; ++u) {
            hp1A[u] = hn1A[u]; hp2A[u] = hn2A[u];
            hp1B[u] = hn1B[u]; hp2B[u] = hn2B[u];
        }
    }

    // ---------- relu -> linear -> relu  (wlin pre-scaled by 0.5 for h~) ----
    float accA = c_w.blin, accB = c_w.blin;
#pragma unroll
    for (int u = 0; u < 8; ++u) {
        float hA, hB, d;
        unpack2(hp2A[u], hA, d);
        unpack2(hp2B[u], hB, d);
        accA = fmaf(c_w.wlin[u], fmaxf(hA, 0.0f), accA);
        accB = fmaf(c_w.wlin[u], fmaxf(hB, 0.0f), accB);
    }
    if (vA) out[bA] = fmaxf(accA, 0.0f);
    if (vB) out[bB] = fmaxf(accB, 0.0f);
}

extern "C" void kernel_launch(void* const* d_in, const int* in_sizes, int n_in,
                              void* d_out, int out_size) {
    const float* X     = (const float*)d_in[0];
    const float* W_ih0 = (const float*)d_in[1];
    const float* W_hh0 = (const float*)d_in[2];
    const float* b_ih0 = (const float*)d_in[3];
    const float* b_hh0 = (const float*)d_in[4];
    const float* W_ih1 = (const float*)d_in[5];
    const float* W_hh1 = (const float*)d_in[6];
    const float* b_ih1 = (const float*)d_in[7];
    const float* b_hh1 = (const float*)d_in[8];
    const float* W_lin = (const float*)d_in[9];
    const float* b_lin = (const float*)d_in[10];

    int Bn = out_size;

    prep_weights_kernel<<<1, 256>>>(
        W_ih0, W_hh0, b_ih0, b_hh0,
        W_ih1, W_hh1, b_ih1, b_hh1, W_lin, b_lin);

    void* src = nullptr;
    cudaGetSymbolAddress(&src, g_wtmp);
    cudaMemcpyToSymbolAsync(c_w, src, sizeof(WPack), 0,
                            cudaMemcpyDeviceToDevice, 0);

    int blocks = (Bn + 511) / 512;
    lstm_fused_kernel<<<blocks, 256>>>(X, (float*)d_out, Bn);
}